// round 1
// baseline (speedup 1.0000x reference)
#include <cuda_runtime.h>

#define BB 2
#define SS 2048
#define HH 1024
#define NH 16
#define HD 64
#define MM (BB*SS)   // 4096 rows

// Scratch (allocation is forbidden; use __device__ globals)
__device__ float g_Wd[HH*HH];
__device__ float g_bd[HH];
__device__ float g_D[(size_t)MM*HH];
__device__ float g_V[(size_t)MM*HH];
__device__ float g_C[(size_t)MM*HH];

// Wd = Wq - Wk, bd = bq - bk
__global__ void sub_wb_kernel(const float* __restrict__ Wq, const float* __restrict__ Wk,
                              const float* __restrict__ bq, const float* __restrict__ bk) {
    int i = blockIdx.x * blockDim.x + threadIdx.x;
    if (i < HH*HH) g_Wd[i] = Wq[i] - Wk[i];
    if (i < HH)    g_bd[i] = bq[i] - bk[i];
}

// C[M,1024] = A[M,1024] @ W[1024,1024] + bias
// BM=BN=64, BK=16, 256 threads, 4x4 register tile per thread.
__global__ void gemm_bias_kernel(const float* __restrict__ A, const float* __restrict__ W,
                                 const float* __restrict__ bias, float* __restrict__ C) {
    const int BM = 64, BN = 64, BK = 16;
    __shared__ float As[BM][BK + 1];   // pad: reads As[r][kk] vary r
    __shared__ float Bs[BK][BN];
    int tid = threadIdx.x;
    int tx = tid & 15, ty = tid >> 4;
    int row0 = blockIdx.y * BM, col0 = blockIdx.x * BN;

    float acc[4][4] = {};
    for (int k0 = 0; k0 < HH; k0 += BK) {
        #pragma unroll
        for (int i = 0; i < 4; i++) {               // 64x16 A tile
            int idx = tid + i * 256;
            int r = idx >> 4, c = idx & 15;
            As[r][c] = A[(size_t)(row0 + r) * HH + k0 + c];
        }
        #pragma unroll
        for (int i = 0; i < 4; i++) {               // 16x64 W tile
            int idx = tid + i * 256;
            int r = idx >> 6, c = idx & 63;
            Bs[r][c] = W[(size_t)(k0 + r) * HH + col0 + c];
        }
        __syncthreads();
        #pragma unroll
        for (int kk = 0; kk < BK; kk++) {
            float a[4], b[4];
            #pragma unroll
            for (int i = 0; i < 4; i++) a[i] = As[ty * 4 + i][kk];
            #pragma unroll
            for (int j = 0; j < 4; j++) b[j] = Bs[kk][tx * 4 + j];
            #pragma unroll
            for (int i = 0; i < 4; i++)
                #pragma unroll
                for (int j = 0; j < 4; j++) acc[i][j] += a[i] * b[j];
        }
        __syncthreads();
    }
    #pragma unroll
    for (int i = 0; i < 4; i++)
        #pragma unroll
        for (int j = 0; j < 4; j++)
            C[(size_t)(row0 + ty * 4 + i) * HH + col0 + tx * 4 + j] =
                acc[i][j] + bias[col0 + tx * 4 + j];
}

// Fused anti-causal gaussian attention.
// ctx[q,:] = sum_{k>q} exp(-0.5 * D_q . D_k) * V[k,:]   per (b, h)
// Q-tile = 64 rows, K-tile = 32 keys. 256 threads (16x16).
// smem: Dq 16KB + DkP 8.3KB (Dk then P^T, reused) + Vs 8KB = ~32.6KB
__global__ void attn_kernel(const float* __restrict__ D, const float* __restrict__ V,
                            float* __restrict__ C) {
    __shared__ float Dq[64][64];
    __shared__ float DkP[32][65];
    __shared__ float Vs[32][64];

    int qb = blockIdx.x, h = blockIdx.y, b = blockIdx.z;
    int q0 = qb * 64;
    int tid = threadIdx.x;
    int tx = tid & 15, ty = tid >> 4;

    const float* Dbase = D + (size_t)b * SS * HH + h * HD;
    const float* Vbase = V + (size_t)b * SS * HH + h * HD;

    // Load Dq tile [64 rows x 64 dims] (coalesced)
    #pragma unroll
    for (int i = 0; i < 16; i++) {
        int idx = tid + i * 256;
        int r = idx >> 6, c = idx & 63;
        Dq[r][c] = Dbase[(size_t)(q0 + r) * HH + c];
    }

    float acc[4][4] = {};
    for (int k0 = q0; k0 < SS; k0 += 32) {
        __syncthreads();   // prev-iter P@V reads done before overwriting DkP/Vs
        #pragma unroll
        for (int i = 0; i < 8; i++) {              // 32x64 Dk and V tiles
            int idx = tid + i * 256;
            int r = idx >> 6, c = idx & 63;
            DkP[r][c] = Dbase[(size_t)(k0 + r) * HH + c];
            Vs[r][c]  = Vbase[(size_t)(k0 + r) * HH + c];
        }
        __syncthreads();

        // S tile [64q x 32k]: each thread rows ty*4+i, cols tx*2+j
        float s[4][2] = {};
        #pragma unroll 8
        for (int d = 0; d < 64; d++) {
            float a[4], bk2[2];
            #pragma unroll
            for (int i = 0; i < 4; i++) a[i] = Dq[ty * 4 + i][d];
            #pragma unroll
            for (int j = 0; j < 2; j++) bk2[j] = DkP[tx * 2 + j][d];
            #pragma unroll
            for (int i = 0; i < 4; i++)
                #pragma unroll
                for (int j = 0; j < 2; j++) s[i][j] += a[i] * bk2[j];
        }
        __syncthreads();   // done reading Dk; buffer reused for P^T

        // mask (k > q strictly) + exp; store P^T[k][q] into DkP
        #pragma unroll
        for (int i = 0; i < 4; i++)
            #pragma unroll
            for (int j = 0; j < 2; j++) {
                int q = q0 + ty * 4 + i;
                int k = k0 + tx * 2 + j;
                float w = (k > q) ? __expf(-0.5f * s[i][j]) : 0.0f;
                DkP[tx * 2 + j][ty * 4 + i] = w;
            }
        __syncthreads();

        // ctx += P @ V : acc rows ty*4+i, cols tx*4+j
        #pragma unroll 8
        for (int k = 0; k < 32; k++) {
            float a[4], bv[4];
            #pragma unroll
            for (int i = 0; i < 4; i++) a[i] = DkP[k][ty * 4 + i];
            #pragma unroll
            for (int j = 0; j < 4; j++) bv[j] = Vs[k][tx * 4 + j];
            #pragma unroll
            for (int i = 0; i < 4; i++)
                #pragma unroll
                for (int j = 0; j < 4; j++) acc[i][j] += a[i] * bv[j];
        }
    }

    // Store ctx directly in merged [B,S,H] layout (head h occupies cols h*64..)
    float* Cbase = C + (size_t)b * SS * HH + h * HD;
    #pragma unroll
    for (int i = 0; i < 4; i++)
        #pragma unroll
        for (int j = 0; j < 4; j++)
            Cbase[(size_t)(q0 + ty * 4 + i) * HH + tx * 4 + j] = acc[i][j];
}

extern "C" void kernel_launch(void* const* d_in, const int* in_sizes, int n_in,
                              void* d_out, int out_size) {
    const float* x  = (const float*)d_in[0];
    const float* Wq = (const float*)d_in[1];
    const float* bq = (const float*)d_in[2];
    const float* Wk = (const float*)d_in[3];
    const float* bk = (const float*)d_in[4];
    const float* Wv = (const float*)d_in[5];
    const float* bv = (const float*)d_in[6];
    const float* Wo = (const float*)d_in[7];
    const float* bo = (const float*)d_in[8];
    float* out = (float*)d_out;

    float *pWd, *pbd, *pD, *pV, *pC;
    cudaGetSymbolAddress((void**)&pWd, g_Wd);
    cudaGetSymbolAddress((void**)&pbd, g_bd);
    cudaGetSymbolAddress((void**)&pD,  g_D);
    cudaGetSymbolAddress((void**)&pV,  g_V);
    cudaGetSymbolAddress((void**)&pC,  g_C);

    // 1. Wd = Wq - Wk, bd = bq - bk
    sub_wb_kernel<<<(HH*HH + 255) / 256, 256>>>(Wq, Wk, bq, bk);

    // 2. D = x @ Wd + bd ; V = x @ Wv + bv
    dim3 ggrid(HH / 64, MM / 64);
    gemm_bias_kernel<<<ggrid, 256>>>(x, pWd, pbd, pD);
    gemm_bias_kernel<<<ggrid, 256>>>(x, Wv, bv, pV);

    // 3. fused attention -> ctx in [B,S,H] layout
    dim3 agrid(SS / 64, NH, BB);
    attn_kernel<<<agrid, 256>>>(pD, pV, pC);

    // 4. out = ctx @ Wo + bo
    gemm_bias_kernel<<<ggrid, 256>>>(pC, Wo, bo, out);
}

// round 3
// speedup vs baseline: 2.0443x; 2.0443x over previous
#include <cuda_runtime.h>
#include <cstdint>

#define BB 2
#define SS 2048
#define HH 1024
#define NH 16
#define HD 64
#define MM (BB*SS)   // 4096 rows

// Scratch (allocation is forbidden; use __device__ globals)
__device__ float g_Wd[HH*HH];
__device__ float g_bd[HH];
__device__ float g_D[(size_t)MM*HH];
__device__ float g_V[(size_t)MM*HH];
__device__ float g_C[(size_t)MM*HH];

__device__ __forceinline__ uint32_t f2tf32(float x) {
    uint32_t r;
    asm("cvt.rna.tf32.f32 %0, %1;" : "=r"(r) : "f"(x));
    return r;
}
// split x = hi + lo, both tf32-representable
__device__ __forceinline__ void tf32split(float x, uint32_t& hi, uint32_t& lo) {
    hi = f2tf32(x);
    lo = f2tf32(x - __uint_as_float(hi));
}

__device__ __forceinline__ void mma8(float* c,
                                     uint32_t a0, uint32_t a1, uint32_t a2, uint32_t a3,
                                     uint32_t b0, uint32_t b1) {
    asm volatile(
        "mma.sync.aligned.m16n8k8.row.col.f32.tf32.tf32.f32 "
        "{%0,%1,%2,%3}, {%4,%5,%6,%7}, {%8,%9}, {%0,%1,%2,%3};"
        : "+f"(c[0]), "+f"(c[1]), "+f"(c[2]), "+f"(c[3])
        : "r"(a0), "r"(a1), "r"(a2), "r"(a3), "r"(b0), "r"(b1));
}

// Wd = Wq - Wk, bd = bq - bk
__global__ void sub_wb_kernel(const float* __restrict__ Wq, const float* __restrict__ Wk,
                              const float* __restrict__ bq, const float* __restrict__ bk) {
    int i = blockIdx.x * blockDim.x + threadIdx.x;
    if (i < HH*HH) g_Wd[i] = Wq[i] - Wk[i];
    if (i < HH)    g_bd[i] = bq[i] - bk[i];
}

// ---------------------------------------------------------------------------
// C[4096,1024] = A @ W + bias   (tf32 tensor-core; X3 => 3xTF32 split prec)
// Block 128x128, 4 warps (2x2), warp tile 64x64, BK=16.
// Smem tiles stored as raw fp32 [k][m]/[k][n], width 136 (stride%32==8 ->
// fragment pattern bank = 8*(l%4)+(l/4), conflict-free). Conversion to tf32
// (and hi/lo split for X3) happens at fragment-load time in registers.
// ---------------------------------------------------------------------------
template<bool X3>
__global__ __launch_bounds__(128) void gemm_tc(const float* __restrict__ A,
                                               const float* __restrict__ W,
                                               const float* __restrict__ bias,
                                               float* __restrict__ C) {
    __shared__ float As[16][136];   // [k][m]
    __shared__ float Bs[16][136];   // [k][n]
    int tid = threadIdx.x, lane = tid & 31, w = tid >> 5;
    int wm = (w & 1) * 64, wn = (w >> 1) * 64;
    int row0 = blockIdx.y * 128, col0 = blockIdx.x * 128;

    float acc[4][8][4] = {};

    for (int k0 = 0; k0 < HH; k0 += 16) {
        __syncthreads();
        // A tile: 128(m) x 16(k) -> As[k][m]
        #pragma unroll
        for (int i = 0; i < 4; i++) {
            int f = tid + i * 128;           // float4 index, 512 total
            int r = f >> 2, cg = (f & 3) * 4;
            float4 v = *(const float4*)&A[(size_t)(row0 + r) * HH + k0 + cg];
            As[cg + 0][r] = v.x;
            As[cg + 1][r] = v.y;
            As[cg + 2][r] = v.z;
            As[cg + 3][r] = v.w;
        }
        // B tile: 16(k) x 128(n) -> Bs[k][n]
        #pragma unroll
        for (int i = 0; i < 4; i++) {
            int f = tid + i * 128;
            int r = f >> 5, cg = (f & 31) * 4;
            float4 v = *(const float4*)&W[(size_t)(k0 + r) * HH + col0 + cg];
            Bs[r][cg + 0] = v.x;
            Bs[r][cg + 1] = v.y;
            Bs[r][cg + 2] = v.z;
            Bs[r][cg + 3] = v.w;
        }
        __syncthreads();

        #pragma unroll
        for (int kk = 0; kk < 16; kk += 8) {
            float afv[4][4], bfv[8][2];
            #pragma unroll
            for (int mt = 0; mt < 4; mt++) {
                int m = wm + mt * 16 + (lane >> 2);
                afv[mt][0] = As[kk +     (lane & 3)][m];
                afv[mt][1] = As[kk +     (lane & 3)][m + 8];
                afv[mt][2] = As[kk + 4 + (lane & 3)][m];
                afv[mt][3] = As[kk + 4 + (lane & 3)][m + 8];
            }
            #pragma unroll
            for (int nt = 0; nt < 8; nt++) {
                int n = wn + nt * 8 + (lane >> 2);
                bfv[nt][0] = Bs[kk +     (lane & 3)][n];
                bfv[nt][1] = Bs[kk + 4 + (lane & 3)][n];
            }
            if (X3) {
                uint32_t ah[4][4], al[4][4], bh[8][2], bl[8][2];
                #pragma unroll
                for (int mt = 0; mt < 4; mt++)
                    #pragma unroll
                    for (int i = 0; i < 4; i++) tf32split(afv[mt][i], ah[mt][i], al[mt][i]);
                #pragma unroll
                for (int nt = 0; nt < 8; nt++)
                    #pragma unroll
                    for (int j = 0; j < 2; j++) tf32split(bfv[nt][j], bh[nt][j], bl[nt][j]);
                #pragma unroll
                for (int mt = 0; mt < 4; mt++)
                    #pragma unroll
                    for (int nt = 0; nt < 8; nt++) {
                        mma8(acc[mt][nt], ah[mt][0], ah[mt][1], ah[mt][2], ah[mt][3],
                             bh[nt][0], bh[nt][1]);
                        mma8(acc[mt][nt], ah[mt][0], ah[mt][1], ah[mt][2], ah[mt][3],
                             bl[nt][0], bl[nt][1]);
                        mma8(acc[mt][nt], al[mt][0], al[mt][1], al[mt][2], al[mt][3],
                             bh[nt][0], bh[nt][1]);
                    }
            } else {
                uint32_t ah[4][4], bh[8][2];
                #pragma unroll
                for (int mt = 0; mt < 4; mt++)
                    #pragma unroll
                    for (int i = 0; i < 4; i++) ah[mt][i] = f2tf32(afv[mt][i]);
                #pragma unroll
                for (int nt = 0; nt < 8; nt++)
                    #pragma unroll
                    for (int j = 0; j < 2; j++) bh[nt][j] = f2tf32(bfv[nt][j]);
                #pragma unroll
                for (int mt = 0; mt < 4; mt++)
                    #pragma unroll
                    for (int nt = 0; nt < 8; nt++)
                        mma8(acc[mt][nt], ah[mt][0], ah[mt][1], ah[mt][2], ah[mt][3],
                             bh[nt][0], bh[nt][1]);
            }
        }
    }

    #pragma unroll
    for (int mt = 0; mt < 4; mt++) {
        int r = row0 + wm + mt * 16 + (lane >> 2);
        #pragma unroll
        for (int nt = 0; nt < 8; nt++) {
            int cb = col0 + wn + nt * 8 + 2 * (lane & 3);
            C[(size_t)r       * HH + cb    ] = acc[mt][nt][0] + bias[cb];
            C[(size_t)r       * HH + cb + 1] = acc[mt][nt][1] + bias[cb + 1];
            C[(size_t)(r + 8) * HH + cb    ] = acc[mt][nt][2] + bias[cb];
            C[(size_t)(r + 8) * HH + cb + 1] = acc[mt][nt][3] + bias[cb + 1];
        }
    }
}

// ---------------------------------------------------------------------------
// Fused anti-causal gaussian attention.
// ctx[q,:] = sum_{k>q} exp(-0.5 * D_q . D_k) * V[k,:]   per (b, h)
// QK in 3xTF32 split precision (s feeds exp, which amplifies error);
// PV in plain tf32. Block: 64 q-rows, 4 warps, K-tile 64.
// Smem stored as raw fp32; cvt/split at fragment-load time.
// Dq/Dk/Ps width 68 (stride%32==4, conflict-free for a/b frag patterns),
// Vs width 72 (stride%32==8, conflict-free for b-frag k-major pattern).
// ---------------------------------------------------------------------------
__global__ __launch_bounds__(128) void attn_tc(const float* __restrict__ D,
                                               const float* __restrict__ V,
                                               float* __restrict__ C) {
    extern __shared__ float sm[];
    float (*Dq)[68] = (float(*)[68])sm;              // 64x68
    float (*Dk)[68] = (float(*)[68])(sm + 64*68);    // 64x68
    float (*Ps)[68] = (float(*)[68])(sm + 2*64*68);  // 64x68
    float (*Vs)[72] = (float(*)[72])(sm + 3*64*68);  // 64x72

    int tid = threadIdx.x, lane = tid & 31, w = tid >> 5;
    int q0 = blockIdx.x * 64, h = blockIdx.y, b = blockIdx.z;
    const float* Db = D + (size_t)b * SS * HH + h * HD;
    const float* Vb = V + (size_t)b * SS * HH + h * HD;

    // Load Dq tile [64 x 64]
    #pragma unroll
    for (int i = 0; i < 8; i++) {
        int f = tid + i * 128;              // float4 index, 1024 total
        int r = f >> 4, cg = (f & 15) * 4;
        float4 v = *(const float4*)&Db[(size_t)(q0 + r) * HH + cg];
        Dq[r][cg + 0] = v.x; Dq[r][cg + 1] = v.y;
        Dq[r][cg + 2] = v.z; Dq[r][cg + 3] = v.w;
    }

    float ctx[8][4] = {};
    int qrow = w * 16 + (lane >> 2);

    for (int k0 = q0; k0 < SS; k0 += 64) {
        __syncthreads();   // prev-iter Dk/Vs/Ps reads done
        #pragma unroll
        for (int i = 0; i < 8; i++) {
            int f = tid + i * 128;
            int r = f >> 4, cg = (f & 15) * 4;
            float4 v = *(const float4*)&Db[(size_t)(k0 + r) * HH + cg];
            Dk[r][cg + 0] = v.x; Dk[r][cg + 1] = v.y;
            Dk[r][cg + 2] = v.z; Dk[r][cg + 3] = v.w;
            float4 u = *(const float4*)&Vb[(size_t)(k0 + r) * HH + cg];
            Vs[r][cg + 0] = u.x; Vs[r][cg + 1] = u.y;
            Vs[r][cg + 2] = u.z; Vs[r][cg + 3] = u.w;
        }
        __syncthreads();

        // S[16q x 64k] per warp = Dq . Dk^T over d=64   (3xTF32)
        float s[8][4] = {};
        #pragma unroll
        for (int kk = 0; kk < 64; kk += 8) {
            float av[4];
            av[0] = Dq[qrow    ][kk +     (lane & 3)];
            av[1] = Dq[qrow + 8][kk +     (lane & 3)];
            av[2] = Dq[qrow    ][kk + 4 + (lane & 3)];
            av[3] = Dq[qrow + 8][kk + 4 + (lane & 3)];
            uint32_t ah[4], al[4];
            #pragma unroll
            for (int i = 0; i < 4; i++) tf32split(av[i], ah[i], al[i]);
            #pragma unroll
            for (int nt = 0; nt < 8; nt++) {
                float b0v = Dk[nt * 8 + (lane >> 2)][kk +     (lane & 3)];
                float b1v = Dk[nt * 8 + (lane >> 2)][kk + 4 + (lane & 3)];
                uint32_t bh0, bl0, bh1, bl1;
                tf32split(b0v, bh0, bl0);
                tf32split(b1v, bh1, bl1);
                mma8(s[nt], ah[0], ah[1], ah[2], ah[3], bh0, bh1);
                mma8(s[nt], ah[0], ah[1], ah[2], ah[3], bl0, bl1);
                mma8(s[nt], al[0], al[1], al[2], al[3], bh0, bh1);
            }
        }

        // mask (k > q strictly) + exp -> Ps (warp-private rows)
        #pragma unroll
        for (int nt = 0; nt < 8; nt++) {
            #pragma unroll
            for (int i = 0; i < 4; i++) {
                int roff = (i >= 2) ? 8 : 0;
                int qq = q0 + qrow + roff;
                int kg = k0 + nt * 8 + 2 * (lane & 3) + (i & 1);
                float p = (kg > qq) ? __expf(-0.5f * s[nt][i]) : 0.0f;
                Ps[qrow + roff][nt * 8 + 2 * (lane & 3) + (i & 1)] = p;
            }
        }
        __syncwarp();

        // ctx += P @ V   (plain tf32; reduction over 64 keys)
        #pragma unroll
        for (int kk = 0; kk < 64; kk += 8) {
            uint32_t a0 = f2tf32(Ps[qrow    ][kk +     (lane & 3)]);
            uint32_t a1 = f2tf32(Ps[qrow + 8][kk +     (lane & 3)]);
            uint32_t a2 = f2tf32(Ps[qrow    ][kk + 4 + (lane & 3)]);
            uint32_t a3 = f2tf32(Ps[qrow + 8][kk + 4 + (lane & 3)]);
            #pragma unroll
            for (int nt = 0; nt < 8; nt++) {
                uint32_t b0 = f2tf32(Vs[kk +     (lane & 3)][nt * 8 + (lane >> 2)]);
                uint32_t b1 = f2tf32(Vs[kk + 4 + (lane & 3)][nt * 8 + (lane >> 2)]);
                mma8(ctx[nt], a0, a1, a2, a3, b0, b1);
            }
        }
    }

    // Store ctx in merged [B,S,H] layout
    float* Cb = C + (size_t)b * SS * HH + h * HD;
    #pragma unroll
    for (int nt = 0; nt < 8; nt++) {
        int r = q0 + qrow;
        int c = nt * 8 + 2 * (lane & 3);
        Cb[(size_t)r       * HH + c    ] = ctx[nt][0];
        Cb[(size_t)r       * HH + c + 1] = ctx[nt][1];
        Cb[(size_t)(r + 8) * HH + c    ] = ctx[nt][2];
        Cb[(size_t)(r + 8) * HH + c + 1] = ctx[nt][3];
    }
}

static const int ATTN_SMEM = (3 * 64 * 68 + 64 * 72) * 4;   // 70656 bytes

extern "C" void kernel_launch(void* const* d_in, const int* in_sizes, int n_in,
                              void* d_out, int out_size) {
    const float* x  = (const float*)d_in[0];
    const float* Wq = (const float*)d_in[1];
    const float* bq = (const float*)d_in[2];
    const float* Wk = (const float*)d_in[3];
    const float* bk = (const float*)d_in[4];
    const float* Wv = (const float*)d_in[5];
    const float* bv = (const float*)d_in[6];
    const float* Wo = (const float*)d_in[7];
    const float* bo = (const float*)d_in[8];
    float* out = (float*)d_out;

    float *pWd, *pbd, *pD, *pV, *pC;
    cudaGetSymbolAddress((void**)&pWd, g_Wd);
    cudaGetSymbolAddress((void**)&pbd, g_bd);
    cudaGetSymbolAddress((void**)&pD,  g_D);
    cudaGetSymbolAddress((void**)&pV,  g_V);
    cudaGetSymbolAddress((void**)&pC,  g_C);

    static bool attr_set = false;
    if (!attr_set) {
        cudaFuncSetAttribute(attn_tc, cudaFuncAttributeMaxDynamicSharedMemorySize, ATTN_SMEM);
        attr_set = true;
    }

    // 1. Wd = Wq - Wk, bd = bq - bk
    sub_wb_kernel<<<(HH*HH + 255) / 256, 256>>>(Wq, Wk, bq, bk);

    // 2. D = x @ Wd + bd (3xTF32) ; V = x @ Wv + bv (tf32)
    dim3 ggrid(HH / 128, MM / 128);
    gemm_tc<true ><<<ggrid, 128>>>(x, pWd, pbd, pD);
    gemm_tc<false><<<ggrid, 128>>>(x, Wv, bv, pV);

    // 3. fused attention -> ctx in [B,S,H] layout
    dim3 agrid(SS / 64, NH, BB);
    attn_tc<<<agrid, 128, ATTN_SMEM>>>(pD, pV, pC);

    // 4. out = ctx @ Wo + bo (tf32)
    gemm_tc<false><<<ggrid, 128>>>(pC, Wo, bo, out);
}

// round 4
// speedup vs baseline: 2.0887x; 1.0217x over previous
#include <cuda_runtime.h>
#include <cstdint>

#define BB 2
#define SS 2048
#define HH 1024
#define NH 16
#define HD 64
#define MM (BB*SS)   // 4096 rows

// Scratch (allocation is forbidden; use __device__ globals)
__device__ float g_Wd[HH*HH];
__device__ float g_bd[HH];
__device__ float g_D[(size_t)MM*HH];
__device__ float g_V[(size_t)MM*HH];
__device__ float g_C[(size_t)MM*HH];

__device__ __forceinline__ uint32_t f2tf32(float x) {
    uint32_t r;
    asm("cvt.rna.tf32.f32 %0, %1;" : "=r"(r) : "f"(x));
    return r;
}
// split x = hi + lo, both tf32-representable
__device__ __forceinline__ void tf32split(float x, uint32_t& hi, uint32_t& lo) {
    hi = f2tf32(x);
    lo = f2tf32(x - __uint_as_float(hi));
}

__device__ __forceinline__ void mma8(float* c,
                                     uint32_t a0, uint32_t a1, uint32_t a2, uint32_t a3,
                                     uint32_t b0, uint32_t b1) {
    asm volatile(
        "mma.sync.aligned.m16n8k8.row.col.f32.tf32.tf32.f32 "
        "{%0,%1,%2,%3}, {%4,%5,%6,%7}, {%8,%9}, {%0,%1,%2,%3};"
        : "+f"(c[0]), "+f"(c[1]), "+f"(c[2]), "+f"(c[3])
        : "r"(a0), "r"(a1), "r"(a2), "r"(a3), "r"(b0), "r"(b1));
}

// Wd = Wq - Wk, bd = bq - bk
__global__ void sub_wb_kernel(const float* __restrict__ Wq, const float* __restrict__ Wk,
                              const float* __restrict__ bq, const float* __restrict__ bk) {
    int i = blockIdx.x * blockDim.x + threadIdx.x;
    if (i < HH*HH) g_Wd[i] = Wq[i] - Wk[i];
    if (i < HH)    g_bd[i] = bq[i] - bk[i];
}

// ---------------------------------------------------------------------------
// C[4096,1024] = A @ W + bias  (tf32 TC; X3 = 3xTF32 split precision)
// Block 128x128, 256 threads (8 warps, 2x4), warp tile 64x32, BK=16.
// All cvt/split done at tile-load time. X3 tiles store hi/lo interleaved
// ([k][2m] / [k][2n], width 264: stride%32==8 -> conflict-free LDS.64 frags).
// Plain tiles store tf32 (width 136, same bank property for LDS.32).
// ---------------------------------------------------------------------------
template<bool X3>
__global__ __launch_bounds__(256) void gemm_tc(const float* __restrict__ A,
                                               const float* __restrict__ W,
                                               const float* __restrict__ bias,
                                               float* __restrict__ C) {
    const int AW = X3 ? 264 : 136;
    __shared__ uint32_t As[16 * (X3 ? 264 : 136)];
    __shared__ uint32_t Bs[16 * (X3 ? 264 : 136)];
    int tid = threadIdx.x, lane = tid & 31, w = tid >> 5;
    int la3 = lane & 3, l4 = lane >> 2;
    int wm = (w & 1) * 64, wn = (w >> 1) * 32;
    int row0 = blockIdx.y * 128, col0 = blockIdx.x * 128;

    float acc[4][4][4] = {};

    for (int k0 = 0; k0 < HH; k0 += 16) {
        __syncthreads();
        // A tile: 128(m) x 16(k) -> As[k][m] (512 float4, 2/thread)
        #pragma unroll
        for (int i = 0; i < 2; i++) {
            int f = tid + i * 256;
            int r = f >> 2, cg = (f & 3) * 4;
            float4 v = *(const float4*)&A[(size_t)(row0 + r) * HH + k0 + cg];
            float vv[4] = {v.x, v.y, v.z, v.w};
            if (X3) {
                #pragma unroll
                for (int j = 0; j < 4; j++) {
                    uint32_t h, l; tf32split(vv[j], h, l);
                    *(uint2*)&As[(cg + j) * AW + 2 * r] = make_uint2(h, l);
                }
            } else {
                #pragma unroll
                for (int j = 0; j < 4; j++) As[(cg + j) * AW + r] = f2tf32(vv[j]);
            }
        }
        // B tile: 16(k) x 128(n) -> Bs[k][n]
        #pragma unroll
        for (int i = 0; i < 2; i++) {
            int f = tid + i * 256;
            int r = f >> 5, cg = (f & 31) * 4;
            float4 v = *(const float4*)&W[(size_t)(k0 + r) * HH + col0 + cg];
            float vv[4] = {v.x, v.y, v.z, v.w};
            if (X3) {
                uint32_t h[4], l[4];
                #pragma unroll
                for (int j = 0; j < 4; j++) tf32split(vv[j], h[j], l[j]);
                *(uint4*)&Bs[r * AW + 2 * cg    ] = make_uint4(h[0], l[0], h[1], l[1]);
                *(uint4*)&Bs[r * AW + 2 * cg + 4] = make_uint4(h[2], l[2], h[3], l[3]);
            } else {
                #pragma unroll
                for (int j = 0; j < 4; j++) Bs[r * AW + cg + j] = f2tf32(vv[j]);
            }
        }
        __syncthreads();

        #pragma unroll
        for (int kk = 0; kk < 16; kk += 8) {
            if (X3) {
                uint32_t bh[4][2], bl[4][2];
                #pragma unroll
                for (int nt = 0; nt < 4; nt++) {
                    int n = wn + nt * 8 + l4;
                    uint2 p0 = *(const uint2*)&Bs[(kk + la3)     * AW + 2 * n];
                    uint2 p1 = *(const uint2*)&Bs[(kk + 4 + la3) * AW + 2 * n];
                    bh[nt][0] = p0.x; bl[nt][0] = p0.y;
                    bh[nt][1] = p1.x; bl[nt][1] = p1.y;
                }
                #pragma unroll
                for (int mt = 0; mt < 4; mt++) {
                    int m = wm + mt * 16 + l4;
                    uint2 a0 = *(const uint2*)&As[(kk + la3)     * AW + 2 * m];
                    uint2 a1 = *(const uint2*)&As[(kk + la3)     * AW + 2 * (m + 8)];
                    uint2 a2 = *(const uint2*)&As[(kk + 4 + la3) * AW + 2 * m];
                    uint2 a3 = *(const uint2*)&As[(kk + 4 + la3) * AW + 2 * (m + 8)];
                    #pragma unroll
                    for (int nt = 0; nt < 4; nt++) {
                        mma8(acc[mt][nt], a0.x, a1.x, a2.x, a3.x, bh[nt][0], bh[nt][1]);
                        mma8(acc[mt][nt], a0.x, a1.x, a2.x, a3.x, bl[nt][0], bl[nt][1]);
                        mma8(acc[mt][nt], a0.y, a1.y, a2.y, a3.y, bh[nt][0], bh[nt][1]);
                    }
                }
            } else {
                uint32_t bf[4][2];
                #pragma unroll
                for (int nt = 0; nt < 4; nt++) {
                    int n = wn + nt * 8 + l4;
                    bf[nt][0] = Bs[(kk + la3)     * AW + n];
                    bf[nt][1] = Bs[(kk + 4 + la3) * AW + n];
                }
                #pragma unroll
                for (int mt = 0; mt < 4; mt++) {
                    int m = wm + mt * 16 + l4;
                    uint32_t a0 = As[(kk + la3)     * AW + m];
                    uint32_t a1 = As[(kk + la3)     * AW + m + 8];
                    uint32_t a2 = As[(kk + 4 + la3) * AW + m];
                    uint32_t a3 = As[(kk + 4 + la3) * AW + m + 8];
                    #pragma unroll
                    for (int nt = 0; nt < 4; nt++)
                        mma8(acc[mt][nt], a0, a1, a2, a3, bf[nt][0], bf[nt][1]);
                }
            }
        }
    }

    #pragma unroll
    for (int mt = 0; mt < 4; mt++) {
        int r = row0 + wm + mt * 16 + l4;
        #pragma unroll
        for (int nt = 0; nt < 4; nt++) {
            int cb = col0 + wn + nt * 8 + 2 * la3;
            C[(size_t)r       * HH + cb    ] = acc[mt][nt][0] + bias[cb];
            C[(size_t)r       * HH + cb + 1] = acc[mt][nt][1] + bias[cb + 1];
            C[(size_t)(r + 8) * HH + cb    ] = acc[mt][nt][2] + bias[cb];
            C[(size_t)(r + 8) * HH + cb + 1] = acc[mt][nt][3] + bias[cb + 1];
        }
    }
}

// ---------------------------------------------------------------------------
// Fused anti-causal gaussian attention (tf32 TC, QK in 3xTF32).
// ctx[q,:] = sum_{k>q} exp(-0.5 * D_q . D_k) * V[k,:]   per (b, h)
// Block: 64 q-rows, 4 warps (16 q-rows each), K-tile 64.
// Dq a-fragments: loaded from gmem ONCE into registers (loop-invariant).
// DkHL: hi/lo interleaved [r][2c]/[2c+1], width 136 -> conflict-free LDS.64.
// Ps/Vs stored pre-converted tf32 (widths 68/72, conflict-free patterns).
// Inner loops contain zero cvt.
// ---------------------------------------------------------------------------
__global__ __launch_bounds__(128, 3) void attn_tc(const float* __restrict__ D,
                                                  const float* __restrict__ V,
                                                  float* __restrict__ C) {
    extern __shared__ uint32_t sm[];
    uint32_t (*DkHL)[136] = (uint32_t(*)[136])sm;                      // 64 x 136
    uint32_t (*Ps)[68]    = (uint32_t(*)[68])(sm + 64 * 136);          // 64 x 68
    uint32_t (*Vs)[72]    = (uint32_t(*)[72])(sm + 64 * 136 + 64 * 68);// 64 x 72

    int tid = threadIdx.x, lane = tid & 31, w = tid >> 5;
    int la3 = lane & 3, l4 = lane >> 2;
    int q0 = blockIdx.x * 64, h = blockIdx.y, b = blockIdx.z;
    const float* Db = D + (size_t)b * SS * HH + h * HD;
    const float* Vb = V + (size_t)b * SS * HH + h * HD;

    int qrow = w * 16 + l4;

    // Dq a-fragments: load once from gmem (fp32, split per kk-step later)
    float av[8][4];
    {
        const float* r0 = Db + (size_t)(q0 + qrow) * HH;
        const float* r8 = r0 + (size_t)8 * HH;
        #pragma unroll
        for (int kk8 = 0; kk8 < 8; kk8++) {
            av[kk8][0] = r0[kk8 * 8 + la3];
            av[kk8][1] = r8[kk8 * 8 + la3];
            av[kk8][2] = r0[kk8 * 8 + 4 + la3];
            av[kk8][3] = r8[kk8 * 8 + 4 + la3];
        }
    }

    float ctx[8][4] = {};

    for (int k0 = q0; k0 < SS; k0 += 64) {
        __syncthreads();   // prev-iter smem reads done
        // Load Dk (split -> DkHL) and V (cvt -> Vs). 1024 float4 each, 8/thread.
        #pragma unroll
        for (int i = 0; i < 8; i++) {
            int f = tid + i * 128;
            int r = f >> 4, cg = (f & 15) * 4;
            float4 dv = *(const float4*)&Db[(size_t)(k0 + r) * HH + cg];
            uint32_t h0, l0, h1, l1, h2, l2, h3, l3;
            tf32split(dv.x, h0, l0); tf32split(dv.y, h1, l1);
            tf32split(dv.z, h2, l2); tf32split(dv.w, h3, l3);
            *(uint4*)&DkHL[r][2 * cg    ] = make_uint4(h0, l0, h1, l1);
            *(uint4*)&DkHL[r][2 * cg + 4] = make_uint4(h2, l2, h3, l3);
            float4 vv = *(const float4*)&Vb[(size_t)(k0 + r) * HH + cg];
            *(uint4*)&Vs[r][cg] = make_uint4(f2tf32(vv.x), f2tf32(vv.y),
                                             f2tf32(vv.z), f2tf32(vv.w));
        }
        __syncthreads();

        // S[16q x 64k] per warp = Dq . Dk^T over d=64  (3xTF32)
        float s[8][4] = {};
        #pragma unroll
        for (int kk8 = 0; kk8 < 8; kk8++) {
            uint32_t aH[4], aL[4];
            #pragma unroll
            for (int i = 0; i < 4; i++) tf32split(av[kk8][i], aH[i], aL[i]);
            #pragma unroll
            for (int nt = 0; nt < 8; nt++) {
                int br = nt * 8 + l4;
                uint2 p0 = *(const uint2*)&DkHL[br][2 * (kk8 * 8 + la3)];
                uint2 p1 = *(const uint2*)&DkHL[br][2 * (kk8 * 8 + 4 + la3)];
                mma8(s[nt], aH[0], aH[1], aH[2], aH[3], p0.x, p1.x);
                mma8(s[nt], aH[0], aH[1], aH[2], aH[3], p0.y, p1.y);
                mma8(s[nt], aL[0], aL[1], aL[2], aL[3], p0.x, p1.x);
            }
        }

        // mask (k > q strictly) + exp -> Ps as tf32 (warp-private rows)
        #pragma unroll
        for (int nt = 0; nt < 8; nt++) {
            int c = nt * 8 + 2 * la3;
            int kg = k0 + c;
            float p00 = (kg     > q0 + qrow)     ? __expf(-0.5f * s[nt][0]) : 0.0f;
            float p01 = (kg + 1 > q0 + qrow)     ? __expf(-0.5f * s[nt][1]) : 0.0f;
            float p10 = (kg     > q0 + qrow + 8) ? __expf(-0.5f * s[nt][2]) : 0.0f;
            float p11 = (kg + 1 > q0 + qrow + 8) ? __expf(-0.5f * s[nt][3]) : 0.0f;
            *(uint2*)&Ps[qrow    ][c] = make_uint2(f2tf32(p00), f2tf32(p01));
            *(uint2*)&Ps[qrow + 8][c] = make_uint2(f2tf32(p10), f2tf32(p11));
        }
        __syncwarp();

        // ctx += P @ V   (plain tf32; reduction over 64 keys)
        #pragma unroll
        for (int kk8 = 0; kk8 < 8; kk8++) {
            int kk = kk8 * 8;
            uint32_t a0 = Ps[qrow    ][kk + la3];
            uint32_t a1 = Ps[qrow + 8][kk + la3];
            uint32_t a2 = Ps[qrow    ][kk + 4 + la3];
            uint32_t a3 = Ps[qrow + 8][kk + 4 + la3];
            #pragma unroll
            for (int nt = 0; nt < 8; nt++) {
                uint32_t b0 = Vs[kk + la3    ][nt * 8 + l4];
                uint32_t b1 = Vs[kk + 4 + la3][nt * 8 + l4];
                mma8(ctx[nt], a0, a1, a2, a3, b0, b1);
            }
        }
    }

    // Store ctx in merged [B,S,H] layout
    float* Cb = C + (size_t)b * SS * HH + h * HD;
    #pragma unroll
    for (int nt = 0; nt < 8; nt++) {
        int r = q0 + qrow;
        int c = nt * 8 + 2 * la3;
        Cb[(size_t)r       * HH + c    ] = ctx[nt][0];
        Cb[(size_t)r       * HH + c + 1] = ctx[nt][1];
        Cb[(size_t)(r + 8) * HH + c    ] = ctx[nt][2];
        Cb[(size_t)(r + 8) * HH + c + 1] = ctx[nt][3];
    }
}

static const int ATTN_SMEM = (64 * 136 + 64 * 68 + 64 * 72) * 4;   // 70656 bytes

extern "C" void kernel_launch(void* const* d_in, const int* in_sizes, int n_in,
                              void* d_out, int out_size) {
    const float* x  = (const float*)d_in[0];
    const float* Wq = (const float*)d_in[1];
    const float* bq = (const float*)d_in[2];
    const float* Wk = (const float*)d_in[3];
    const float* bk = (const float*)d_in[4];
    const float* Wv = (const float*)d_in[5];
    const float* bv = (const float*)d_in[6];
    const float* Wo = (const float*)d_in[7];
    const float* bo = (const float*)d_in[8];
    float* out = (float*)d_out;

    float *pWd, *pbd, *pD, *pV, *pC;
    cudaGetSymbolAddress((void**)&pWd, g_Wd);
    cudaGetSymbolAddress((void**)&pbd, g_bd);
    cudaGetSymbolAddress((void**)&pD,  g_D);
    cudaGetSymbolAddress((void**)&pV,  g_V);
    cudaGetSymbolAddress((void**)&pC,  g_C);

    static bool attr_set = false;
    if (!attr_set) {
        cudaFuncSetAttribute(attn_tc, cudaFuncAttributeMaxDynamicSharedMemorySize, ATTN_SMEM);
        attr_set = true;
    }

    // 1. Wd = Wq - Wk, bd = bq - bk
    sub_wb_kernel<<<(HH*HH + 255) / 256, 256>>>(Wq, Wk, bq, bk);

    // 2. D = x @ Wd + bd (3xTF32) ; V = x @ Wv + bv (tf32)
    dim3 ggrid(HH / 128, MM / 128);
    gemm_tc<true ><<<ggrid, 256>>>(x, pWd, pbd, pD);
    gemm_tc<false><<<ggrid, 256>>>(x, Wv, bv, pV);

    // 3. fused attention -> ctx in [B,S,H] layout
    dim3 agrid(SS / 64, NH, BB);
    attn_tc<<<agrid, 128, ATTN_SMEM>>>(pD, pV, pC);

    // 4. out = ctx @ Wo + bo (tf32)
    gemm_tc<false><<<ggrid, 256>>>(pC, Wo, bo, out);
}